// round 2
// baseline (speedup 1.0000x reference)
#include <cuda_runtime.h>
#include <cuda_bf16.h>

// Problem: BS=64, G=64, L=100, D=64.  NG = BS*G = 4096 groups.
// Key identity: softmax is shift-invariant, so V_last/V_avg/b contribute a
// per-group constant to emb and cancel. attn = softmax_l(seqs[l] . (W2 @ p)).
// => lens, W1, W3, b are unused.

#define NG   4096
#define L    100
#define D    64
#define SPAD 68          // padded row stride in shared (68*4 bytes, 16B aligned)

__device__ float g_q[D];                 // q = W2 @ p   (q[d] = row_d(W2) . p)
__device__ float g_weighted[NG * D];     // attention-pooled rows

// ---------------------------------------------------------------------------
// Kernel 0: q[d] = sum_e W2[d,e] * p[e]    (row-major W2: W2[d*D+e])
// ---------------------------------------------------------------------------
__global__ void qvec_kernel(const float* __restrict__ W2, const float* __restrict__ p) {
    int d = threadIdx.x;
    float acc = 0.f;
#pragma unroll 8
    for (int e = 0; e < D; ++e) acc += W2[d * D + e] * p[e];
    g_q[d] = acc;
}

// ---------------------------------------------------------------------------
// Kernel 1: per-group attention pooling. One block per (b,g). 128 threads.
// ---------------------------------------------------------------------------
__global__ __launch_bounds__(128) void attn_kernel(const float* __restrict__ seqs) {
    __shared__ float s[L * SPAD];     // 27.2 KB tile, padded rows
    __shared__ float attn_sh[128];    // emb, then attn weights
    __shared__ float red[32];
    __shared__ float part[128];

    const int g   = blockIdx.x;
    const int tid = threadIdx.x;
    const int w   = tid >> 5;
    const int lane = tid & 31;

    // ---- load tile: 100*16 float4, coalesced; store with row pad 68 ----
    const float4* src = (const float4*)(seqs + (size_t)g * (L * D));
#pragma unroll
    for (int idx = tid; idx < L * (D / 4); idx += 128) {
        int row = idx >> 4, c4 = idx & 15;
        float4 v = __ldg(src + idx);
        *(float4*)&s[row * SPAD + c4 * 4] = v;
    }

    const float qa = g_q[lane];
    const float qb = g_q[lane + 32];
    __syncthreads();

    // ---- emb[l] = row_l . q  (warp per row, shfl reduce) ----
    for (int l = w; l < L; l += 4) {
        float v = s[l * SPAD + lane] * qa + s[l * SPAD + 32 + lane] * qb;
#pragma unroll
        for (int o = 16; o > 0; o >>= 1) v += __shfl_xor_sync(0xffffffffu, v, o);
        if (lane == 0) attn_sh[l] = v;
    }
    __syncthreads();

    // ---- softmax over L=100 (threads >= L contribute -inf / 0) ----
    float v = (tid < L) ? attn_sh[tid] : -1e30f;
    float m = v;
#pragma unroll
    for (int o = 16; o > 0; o >>= 1) m = fmaxf(m, __shfl_xor_sync(0xffffffffu, m, o));
    if (lane == 0) red[w] = m;
    __syncthreads();
    float vmax = fmaxf(fmaxf(red[0], red[1]), fmaxf(red[2], red[3]));

    float e = (tid < L) ? __expf(v - vmax) : 0.f;
    float sv = e;
#pragma unroll
    for (int o = 16; o > 0; o >>= 1) sv += __shfl_xor_sync(0xffffffffu, sv, o);
    __syncthreads();                      // red[] consumed by all before reuse
    if (lane == 0) red[w] = sv;
    __syncthreads();
    float denom = red[0] + red[1] + red[2] + red[3];
    attn_sh[tid] = e * (1.f / denom);
    __syncthreads();

    // ---- weighted[d] = sum_l attn[l] * s[l][d]  (two halves of L) ----
    const int d    = tid & 63;
    const int half = tid >> 6;
    float acc = 0.f;
    const int l0 = half * 50;
#pragma unroll 10
    for (int l = l0; l < l0 + 50; ++l) acc += attn_sh[l] * s[l * SPAD + d];
    part[tid] = acc;
    __syncthreads();
    if (tid < D) g_weighted[g * D + d] = part[d] + part[64 + d];
}

// ---------------------------------------------------------------------------
// Kernel 2: MLP  out = h0 + relu(relu(h0@Wl0+bl0)@Wl1+bl1),  h0 = X@Wq.
// 128 blocks x 256 threads, 32 rows/block, 4x4 register tiles.
// ---------------------------------------------------------------------------
__global__ __launch_bounds__(256) void mlp_kernel(
    const float* __restrict__ Wq,  const float* __restrict__ Wl0,
    const float* __restrict__ bl0, const float* __restrict__ Wl1,
    const float* __restrict__ bl1, float* __restrict__ out)
{
    __shared__ float sx [32 * 64];
    __shared__ float sh0[32 * 128];
    __shared__ float sh1[32 * 128];

    const int t    = threadIdx.x;
    const int row0 = blockIdx.x * 32;

    // load X tile (32x64) coalesced
    {
        const float4* src = (const float4*)(g_weighted + (size_t)row0 * D);
#pragma unroll
        for (int i = t; i < 32 * 64 / 4; i += 256) ((float4*)sx)[i] = src[i];
    }
    __syncthreads();

    const int tc = t & 31;        // column tile: cols [4*tc, 4*tc+4)
    const int tr = t >> 5;        // row tile:    rows [4*tr, 4*tr+4)
    const int r0 = tr * 4, c0 = tc * 4;

    float acc[4][4];

    // ---- stage 1: h0 = X @ Wq  (K=64) ----
#pragma unroll
    for (int i = 0; i < 4; ++i)
#pragma unroll
        for (int j = 0; j < 4; ++j) acc[i][j] = 0.f;

#pragma unroll 4
    for (int d = 0; d < 64; ++d) {
        float4 wv = __ldg((const float4*)&Wq[d * 128 + c0]);
#pragma unroll
        for (int i = 0; i < 4; ++i) {
            float x = sx[(r0 + i) * 64 + d];   // broadcast within warp
            acc[i][0] += x * wv.x; acc[i][1] += x * wv.y;
            acc[i][2] += x * wv.z; acc[i][3] += x * wv.w;
        }
    }
#pragma unroll
    for (int i = 0; i < 4; ++i)
        *(float4*)&sh0[(r0 + i) * 128 + c0] =
            make_float4(acc[i][0], acc[i][1], acc[i][2], acc[i][3]);
    __syncthreads();

    // ---- stage 2: h1 = relu(h0 @ Wl0 + bl0)  (K=128) ----
    {
        float4 bv = __ldg((const float4*)&bl0[c0]);
#pragma unroll
        for (int i = 0; i < 4; ++i) { acc[i][0] = bv.x; acc[i][1] = bv.y; acc[i][2] = bv.z; acc[i][3] = bv.w; }
    }
#pragma unroll 4
    for (int d = 0; d < 128; ++d) {
        float4 wv = __ldg((const float4*)&Wl0[d * 128 + c0]);
#pragma unroll
        for (int i = 0; i < 4; ++i) {
            float x = sh0[(r0 + i) * 128 + d];
            acc[i][0] += x * wv.x; acc[i][1] += x * wv.y;
            acc[i][2] += x * wv.z; acc[i][3] += x * wv.w;
        }
    }
#pragma unroll
    for (int i = 0; i < 4; ++i)
        *(float4*)&sh1[(r0 + i) * 128 + c0] =
            make_float4(fmaxf(acc[i][0], 0.f), fmaxf(acc[i][1], 0.f),
                        fmaxf(acc[i][2], 0.f), fmaxf(acc[i][3], 0.f));
    __syncthreads();

    // ---- stage 3: h2 = relu(h1 @ Wl1 + bl1); out = h0 + h2 ----
    {
        float4 bv = __ldg((const float4*)&bl1[c0]);
#pragma unroll
        for (int i = 0; i < 4; ++i) { acc[i][0] = bv.x; acc[i][1] = bv.y; acc[i][2] = bv.z; acc[i][3] = bv.w; }
    }
#pragma unroll 4
    for (int d = 0; d < 128; ++d) {
        float4 wv = __ldg((const float4*)&Wl1[d * 128 + c0]);
#pragma unroll
        for (int i = 0; i < 4; ++i) {
            float x = sh1[(r0 + i) * 128 + d];
            acc[i][0] += x * wv.x; acc[i][1] += x * wv.y;
            acc[i][2] += x * wv.z; acc[i][3] += x * wv.w;
        }
    }
#pragma unroll
    for (int i = 0; i < 4; ++i) {
        const float* h0r = &sh0[(r0 + i) * 128 + c0];
        float4 o = make_float4(h0r[0] + fmaxf(acc[i][0], 0.f),
                               h0r[1] + fmaxf(acc[i][1], 0.f),
                               h0r[2] + fmaxf(acc[i][2], 0.f),
                               h0r[3] + fmaxf(acc[i][3], 0.f));
        *(float4*)&out[(size_t)(row0 + r0 + i) * 128 + c0] = o;
    }
}

// ---------------------------------------------------------------------------
extern "C" void kernel_launch(void* const* d_in, const int* in_sizes, int n_in,
                              void* d_out, int out_size) {
    const float* seqs = (const float*)d_in[0];
    // d_in[1] = lens  (unused: cancels in softmax)
    // d_in[2] = W1    (unused)
    const float* W2   = (const float*)d_in[3];
    // d_in[4] = W3    (unused)
    // d_in[5] = b     (unused)
    const float* p    = (const float*)d_in[6];
    const float* Wq   = (const float*)d_in[7];
    const float* Wl0  = (const float*)d_in[8];
    const float* bl0  = (const float*)d_in[9];
    const float* Wl1  = (const float*)d_in[10];
    const float* bl1  = (const float*)d_in[11];
    float* out = (float*)d_out;

    qvec_kernel<<<1, 64>>>(W2, p);
    attn_kernel<<<NG, 128>>>(seqs);
    mlp_kernel<<<NG / 32, 256>>>(Wq, Wl0, bl0, Wl1, bl1, out);
}

// round 4
// speedup vs baseline: 1.5069x; 1.5069x over previous
#include <cuda_runtime.h>
#include <cuda_bf16.h>
#include <cstdint>

// BS=64, G=64, L=100, D=64. NG=4096 groups.
// softmax shift-invariance: V_last/V_avg/b cancel => attn = softmax_l(seqs[l].(W2@p)).
// lens, W1, W3, b unused.

#define NG   4096
#define L    100
#define D    64
#define SPAD 65          // odd stride: conflict-free for both row- and col-direction access

__device__ float g_weighted[NG * D];     // attention-pooled rows

// ---------------------------------------------------------------------------
// cp.async helpers
// ---------------------------------------------------------------------------
__device__ __forceinline__ void cp16(unsigned int s_addr, const void* g) {
    asm volatile("cp.async.cg.shared.global [%0], [%1], 16;\n" :: "r"(s_addr), "l"(g));
}
#define CP_COMMIT() asm volatile("cp.async.commit_group;\n" ::: "memory")
#define CP_WAIT(n)  asm volatile("cp.async.wait_group %0;\n" :: "n"(n) : "memory")

// ---------------------------------------------------------------------------
// Kernel 1: per-group attention pooling + fused q = W2 @ p.
// One block per (b,g). 128 threads.
// ---------------------------------------------------------------------------
__global__ __launch_bounds__(128) void attn_kernel(
    const float* __restrict__ seqs, const float* __restrict__ W2,
    const float* __restrict__ p)
{
    __shared__ float s[L * SPAD];     // 26.0 KB, stride-65 rows
    __shared__ float q_s[D];
    __shared__ float attn_sh[128];
    __shared__ float red[4];
    __shared__ float part[128];

    const int g    = blockIdx.x;
    const int tid  = threadIdx.x;
    const int w    = tid >> 5;
    const int lane = tid & 31;

    // ---- issue tile loads into registers (long-scoreboard latency starts now) ----
    const float4* src = (const float4*)(seqs + (size_t)g * (L * D));
    float4 r[13];
#pragma unroll
    for (int k = 0; k < 13; ++k) {
        int idx = tid + k * 128;
        if (idx < L * (D / 4)) r[k] = __ldg(src + idx);
    }

    // ---- q[d] = row_d(W2) . p  (overlapped with tile-load latency; W2/p L2-hot) ----
    if (tid < D) {
        float acc = 0.f;
        const float4* wrow = (const float4*)(W2 + tid * D);
#pragma unroll
        for (int e4 = 0; e4 < D / 4; ++e4) {
            float4 wv = __ldg(wrow + e4);
            float4 pv = __ldg((const float4*)p + e4);
            acc += wv.x * pv.x + wv.y * pv.y + wv.z * pv.z + wv.w * pv.w;
        }
        q_s[tid] = acc;
    }

    // ---- scatter tile to shared (stride-65 rows, scalar stores) ----
#pragma unroll
    for (int k = 0; k < 13; ++k) {
        int idx = tid + k * 128;
        if (idx < L * (D / 4)) {
            int row = idx >> 4, c4 = idx & 15;
            float* dst = &s[row * SPAD + c4 * 4];
            dst[0] = r[k].x; dst[1] = r[k].y; dst[2] = r[k].z; dst[3] = r[k].w;
        }
    }
    __syncthreads();

    // ---- emb[l]: thread-per-row dot, conflict-free (stride 65 across threads) ----
    float v = -1e30f;
    if (tid < L) {
        float acc = 0.f;
        const float* row = &s[tid * SPAD];
#pragma unroll 16
        for (int d = 0; d < D; ++d) acc += row[d] * q_s[d];
        v = acc;
    }

    // ---- softmax over L=100 across 4 warps ----
    float m = v;
#pragma unroll
    for (int o = 16; o > 0; o >>= 1) m = fmaxf(m, __shfl_xor_sync(0xffffffffu, m, o));
    if (lane == 0) red[w] = m;
    __syncthreads();
    float vmax = fmaxf(fmaxf(red[0], red[1]), fmaxf(red[2], red[3]));
    __syncthreads();

    float e = (tid < L) ? __expf(v - vmax) : 0.f;
    float sv = e;
#pragma unroll
    for (int o = 16; o > 0; o >>= 1) sv += __shfl_xor_sync(0xffffffffu, sv, o);
    if (lane == 0) red[w] = sv;
    __syncthreads();
    float denom = red[0] + red[1] + red[2] + red[3];
    attn_sh[tid] = e * (1.f / denom);
    __syncthreads();

    // ---- weighted[d] = sum_l attn[l] * s[l][d]  (two L-halves; conflict-free) ----
    const int d    = tid & 63;
    const int half = tid >> 6;
    float acc = 0.f;
    const int l0 = half * 50;
#pragma unroll 10
    for (int l = l0; l < l0 + 50; ++l) acc += attn_sh[l] * s[l * SPAD + d];
    part[tid] = acc;
    __syncthreads();
    if (tid < D) g_weighted[g * D + d] = part[d] + part[64 + d];
}

// ---------------------------------------------------------------------------
// Kernel 2: MLP  out = h0 + relu(relu(h0@Wl0+bl0)@Wl1+bl1),  h0 = X@Wq.
// 128 blocks x 256 threads, 32 rows/block, 4x4 register tiles.
// All weights staged in 200KB dynamic shared via cp.async groups.
// ---------------------------------------------------------------------------
__global__ __launch_bounds__(256) void mlp_kernel(
    const float* __restrict__ Wq,  const float* __restrict__ Wl0,
    const float* __restrict__ bl0, const float* __restrict__ Wl1,
    const float* __restrict__ bl1, float* __restrict__ out)
{
    extern __shared__ float smem[];
    float* sx  = smem;             // 32x64    =  2048 f
    float* sh0 = smem + 2048;      // 32x128   =  4096 f
    float* sh1 = smem + 6144;      // 32x128   =  4096 f
    float* wq  = smem + 10240;     // 64x128   =  8192 f
    float* wl0 = smem + 18432;     // 128x128  = 16384 f
    float* wl1 = smem + 34816;     // 128x128  = 16384 f  (total 51200 f = 200 KB)

    const int t    = threadIdx.x;
    const int row0 = blockIdx.x * 32;

    const unsigned int sb = (unsigned int)__cvta_generic_to_shared(smem);

    // ---- async staging: G0 = sx + Wq, G1 = Wl0, G2 = Wl1 ----
    {
        const float4* xs = (const float4*)(g_weighted + (size_t)row0 * D);
#pragma unroll
        for (int i = 0; i < 2; ++i) {
            int idx = t + i * 256;                       // 512 f4
            cp16(sb + (0 + idx * 4) * 4, xs + idx);
        }
#pragma unroll
        for (int i = 0; i < 8; ++i) {
            int idx = t + i * 256;                       // 2048 f4
            cp16(sb + (10240 + idx * 4) * 4, (const float4*)Wq + idx);
        }
        CP_COMMIT();
#pragma unroll
        for (int i = 0; i < 16; ++i) {
            int idx = t + i * 256;                       // 4096 f4
            cp16(sb + (18432 + idx * 4) * 4, (const float4*)Wl0 + idx);
        }
        CP_COMMIT();
#pragma unroll
        for (int i = 0; i < 16; ++i) {
            int idx = t + i * 256;
            cp16(sb + (34816 + idx * 4) * 4, (const float4*)Wl1 + idx);
        }
        CP_COMMIT();
    }

    const int tc = t & 31;        // cols [4*tc, 4*tc+4)
    const int tr = t >> 5;        // rows [4*tr, 4*tr+4)
    const int r0 = tr * 4, c0 = tc * 4;

    float acc[4][4];

    // ---- stage 1: h0 = X @ Wq  (K=64) ----
    CP_WAIT(2);
    __syncthreads();
#pragma unroll
    for (int i = 0; i < 4; ++i)
#pragma unroll
        for (int j = 0; j < 4; ++j) acc[i][j] = 0.f;

#pragma unroll 4
    for (int d = 0; d < 64; ++d) {
        float4 wv = *(const float4*)&wq[d * 128 + c0];
#pragma unroll
        for (int i = 0; i < 4; ++i) {
            float x = sx[(r0 + i) * 64 + d];   // warp-uniform broadcast
            acc[i][0] += x * wv.x; acc[i][1] += x * wv.y;
            acc[i][2] += x * wv.z; acc[i][3] += x * wv.w;
        }
    }
#pragma unroll
    for (int i = 0; i < 4; ++i)
        *(float4*)&sh0[(r0 + i) * 128 + c0] =
            make_float4(acc[i][0], acc[i][1], acc[i][2], acc[i][3]);

    // ---- stage 2: h1 = relu(h0 @ Wl0 + bl0)  (K=128) ----
    CP_WAIT(1);
    __syncthreads();
    {
        float4 bv = __ldg((const float4*)&bl0[c0]);
#pragma unroll
        for (int i = 0; i < 4; ++i) { acc[i][0] = bv.x; acc[i][1] = bv.y; acc[i][2] = bv.z; acc[i][3] = bv.w; }
    }
#pragma unroll 4
    for (int d = 0; d < 128; ++d) {
        float4 wv = *(const float4*)&wl0[d * 128 + c0];
#pragma unroll
        for (int i = 0; i < 4; ++i) {
            float x = sh0[(r0 + i) * 128 + d];
            acc[i][0] += x * wv.x; acc[i][1] += x * wv.y;
            acc[i][2] += x * wv.z; acc[i][3] += x * wv.w;
        }
    }
#pragma unroll
    for (int i = 0; i < 4; ++i)
        *(float4*)&sh1[(r0 + i) * 128 + c0] =
            make_float4(fmaxf(acc[i][0], 0.f), fmaxf(acc[i][1], 0.f),
                        fmaxf(acc[i][2], 0.f), fmaxf(acc[i][3], 0.f));

    // ---- stage 3: h2 = relu(h1 @ Wl1 + bl1); out = h0 + h2 ----
    CP_WAIT(0);
    __syncthreads();
    {
        float4 bv = __ldg((const float4*)&bl1[c0]);
#pragma unroll
        for (int i = 0; i < 4; ++i) { acc[i][0] = bv.x; acc[i][1] = bv.y; acc[i][2] = bv.z; acc[i][3] = bv.w; }
    }
#pragma unroll 4
    for (int d = 0; d < 128; ++d) {
        float4 wv = *(const float4*)&wl1[d * 128 + c0];
#pragma unroll
        for (int i = 0; i < 4; ++i) {
            float x = sh1[(r0 + i) * 128 + d];
            acc[i][0] += x * wv.x; acc[i][1] += x * wv.y;
            acc[i][2] += x * wv.z; acc[i][3] += x * wv.w;
        }
    }
#pragma unroll
    for (int i = 0; i < 4; ++i) {
        const float* h0r = &sh0[(r0 + i) * 128 + c0];
        float4 o = make_float4(h0r[0] + fmaxf(acc[i][0], 0.f),
                               h0r[1] + fmaxf(acc[i][1], 0.f),
                               h0r[2] + fmaxf(acc[i][2], 0.f),
                               h0r[3] + fmaxf(acc[i][3], 0.f));
        *(float4*)&out[(size_t)(row0 + r0 + i) * 128 + c0] = o;
    }
}

// ---------------------------------------------------------------------------
extern "C" void kernel_launch(void* const* d_in, const int* in_sizes, int n_in,
                              void* d_out, int out_size) {
    const float* seqs = (const float*)d_in[0];
    const float* W2   = (const float*)d_in[3];
    const float* p    = (const float*)d_in[6];
    const float* Wq   = (const float*)d_in[7];
    const float* Wl0  = (const float*)d_in[8];
    const float* bl0  = (const float*)d_in[9];
    const float* Wl1  = (const float*)d_in[10];
    const float* bl1  = (const float*)d_in[11];
    float* out = (float*)d_out;

    static bool attr_set = false;
    if (!attr_set) {
        cudaFuncSetAttribute(mlp_kernel,
                             cudaFuncAttributeMaxDynamicSharedMemorySize, 204800);
        attr_set = true;
    }

    attn_kernel<<<NG, 128>>>(seqs, W2, p);
    mlp_kernel<<<NG / 32, 256, 204800>>>(Wq, Wl0, bl0, Wl1, bl1, out);
}

// round 5
// speedup vs baseline: 1.6415x; 1.0893x over previous
#include <cuda_runtime.h>
#include <cuda_bf16.h>
#include <cstdint>

// BS=64, G=64, L=100, D=64. NG=4096 groups.
// softmax shift-invariance: V_last/V_avg/b cancel => attn = softmax_l(seqs[l].(W2@p)).
// lens, W1, W3, b unused.

#define NG   4096
#define L    100
#define D    64

__device__ float g_weighted[NG * D];     // attention-pooled rows

// ---------------------------------------------------------------------------
// cp.async helpers
// ---------------------------------------------------------------------------
__device__ __forceinline__ void cp16(unsigned int s_addr, const void* g) {
    asm volatile("cp.async.cg.shared.global [%0], [%1], 16;\n" :: "r"(s_addr), "l"(g));
}
#define CP_COMMIT() asm volatile("cp.async.commit_group;\n" ::: "memory")
#define CP_WAIT(n)  asm volatile("cp.async.wait_group %0;\n" :: "n"(n) : "memory")

// ---------------------------------------------------------------------------
// Kernel 1: per-group attention pooling + fused q = W2 @ p.
// One block per (b,g), 128 threads. Tile lives in REGISTERS:
//   thread t, chunk k (idx = t + 128k): row_k = (t>>4)+8k, cols [4*(t&15), +4).
// ---------------------------------------------------------------------------
__global__ __launch_bounds__(128) void attn_kernel(
    const float* __restrict__ seqs, const float* __restrict__ W2,
    const float* __restrict__ p)
{
    __shared__ float q_s[D];
    __shared__ float attn_sh[104];       // emb, then attn weights; [100..104) = 0
    __shared__ float red[4];
    __shared__ float part4[4][16][4];    // [warp][c4][comp]

    const int g    = blockIdx.x;
    const int tid  = threadIdx.x;
    const int w    = tid >> 5;
    const int lane = tid & 31;
    const int c4   = tid & 15;           // column group (4 floats)
    const int grp  = tid >> 4;           // row group 0..7

    // ---- issue all tile loads into registers ----
    const float4* src = (const float4*)(seqs + (size_t)g * (L * D));
    float4 r[13];
#pragma unroll
    for (int k = 0; k < 13; ++k) {
        int idx = tid + k * 128;
        if (idx < L * (D / 4)) r[k] = __ldg(src + idx);
        else                   r[k] = make_float4(0.f, 0.f, 0.f, 0.f);
    }

    // ---- q[d] = row_d(W2) . p  (overlaps tile-load latency; W2/p L2-hot) ----
    if (tid < D) {
        float acc = 0.f;
        const float4* wrow = (const float4*)(W2 + tid * D);
#pragma unroll
        for (int e4 = 0; e4 < D / 4; ++e4) {
            float4 wv = __ldg(wrow + e4);
            float4 pv = __ldg((const float4*)p + e4);
            acc += wv.x * pv.x + wv.y * pv.y + wv.z * pv.z + wv.w * pv.w;
        }
        q_s[tid] = acc;
    }
    __syncthreads();

    // ---- emb[row_k]: per-thread partial dot + 16-lane segmented shfl reduce ----
    const float4 q4 = *(const float4*)&q_s[c4 * 4];
#pragma unroll
    for (int k = 0; k < 13; ++k) {
        float v = r[k].x * q4.x + r[k].y * q4.y + r[k].z * q4.z + r[k].w * q4.w;
        v += __shfl_xor_sync(0xffffffffu, v, 1);
        v += __shfl_xor_sync(0xffffffffu, v, 2);
        v += __shfl_xor_sync(0xffffffffu, v, 4);
        v += __shfl_xor_sync(0xffffffffu, v, 8);
        int row = grp + 8 * k;
        if (c4 == 0 && row < L) attn_sh[row] = v;
    }
    __syncthreads();

    // ---- softmax over L=100 ----
    float v = (tid < L) ? attn_sh[tid] : -1e30f;
    float m = v;
#pragma unroll
    for (int o = 16; o > 0; o >>= 1) m = fmaxf(m, __shfl_xor_sync(0xffffffffu, m, o));
    if (lane == 0) red[w] = m;
    __syncthreads();
    float vmax = fmaxf(fmaxf(red[0], red[1]), fmaxf(red[2], red[3]));
    __syncthreads();

    float e = (tid < L) ? __expf(v - vmax) : 0.f;
    float sv = e;
#pragma unroll
    for (int o = 16; o > 0; o >>= 1) sv += __shfl_xor_sync(0xffffffffu, sv, o);
    if (lane == 0) red[w] = sv;
    __syncthreads();
    float inv = 1.f / (red[0] + red[1] + red[2] + red[3]);
    if (tid < L) attn_sh[tid] = e * inv;
    else if (tid < 104) attn_sh[tid] = 0.f;
    __syncthreads();

    // ---- pooling: p4 = sum_k attn[row_k] * r[k]  (registers) ----
    float4 p4 = make_float4(0.f, 0.f, 0.f, 0.f);
#pragma unroll
    for (int k = 0; k < 13; ++k) {
        float a = attn_sh[grp + 8 * k];   // 2 distinct addrs/warp, broadcast
        p4.x += a * r[k].x; p4.y += a * r[k].y;
        p4.z += a * r[k].z; p4.w += a * r[k].w;
    }
    // combine the two row-groups within each warp (lanes l and l+16)
    p4.x += __shfl_xor_sync(0xffffffffu, p4.x, 16);
    p4.y += __shfl_xor_sync(0xffffffffu, p4.y, 16);
    p4.z += __shfl_xor_sync(0xffffffffu, p4.z, 16);
    p4.w += __shfl_xor_sync(0xffffffffu, p4.w, 16);
    if (lane < 16) *(float4*)&part4[w][lane][0] = p4;
    __syncthreads();
    if (tid < D) {
        int ci = tid >> 2, comp = tid & 3;
        float sum = part4[0][ci][comp] + part4[1][ci][comp]
                  + part4[2][ci][comp] + part4[3][ci][comp];
        g_weighted[g * D + tid] = sum;
    }
}

// ---------------------------------------------------------------------------
// Kernel 2: MLP  out = h0 + relu(relu(h0@Wl0+bl0)@Wl1+bl1),  h0 = X@Wq.
// 128 blocks x 512 threads, 32 rows/block, 2x4 register tiles.
// All weights staged in 200KB dynamic shared via cp.async groups.
// ---------------------------------------------------------------------------
__global__ __launch_bounds__(512) void mlp_kernel(
    const float* __restrict__ Wq,  const float* __restrict__ Wl0,
    const float* __restrict__ bl0, const float* __restrict__ Wl1,
    const float* __restrict__ bl1, float* __restrict__ out)
{
    extern __shared__ float smem[];
    float* sx  = smem;             // 32x64    =  2048 f
    float* sh0 = smem + 2048;      // 32x128   =  4096 f
    float* sh1 = smem + 6144;      // 32x128   =  4096 f
    float* wq  = smem + 10240;     // 64x128   =  8192 f
    float* wl0 = smem + 18432;     // 128x128  = 16384 f
    float* wl1 = smem + 34816;     // 128x128  = 16384 f  (total 51200 f = 200 KB)

    const int t    = threadIdx.x;
    const int row0 = blockIdx.x * 32;

    const unsigned int sb = (unsigned int)__cvta_generic_to_shared(smem);

    // ---- async staging: G0 = sx + Wq, G1 = Wl0, G2 = Wl1 ----
    {
        const float4* xs = (const float4*)(g_weighted + (size_t)row0 * D);
        cp16(sb + (0 + t * 4) * 4, xs + t);                    // 512 f4
#pragma unroll
        for (int i = 0; i < 4; ++i) {
            int idx = t + i * 512;                             // 2048 f4
            cp16(sb + (10240 + idx * 4) * 4, (const float4*)Wq + idx);
        }
        CP_COMMIT();
#pragma unroll
        for (int i = 0; i < 8; ++i) {
            int idx = t + i * 512;                             // 4096 f4
            cp16(sb + (18432 + idx * 4) * 4, (const float4*)Wl0 + idx);
        }
        CP_COMMIT();
#pragma unroll
        for (int i = 0; i < 8; ++i) {
            int idx = t + i * 512;
            cp16(sb + (34816 + idx * 4) * 4, (const float4*)Wl1 + idx);
        }
        CP_COMMIT();
    }

    const int tc = t & 31;        // cols [4*tc, 4*tc+4)
    const int wr = t >> 5;        // warp id 0..15 -> rows [2*wr, 2*wr+2)
    const int r0 = wr * 2, c0 = tc * 4;

    float acc[2][4];

    // ---- stage 1: h0 = X @ Wq  (K=64) ----
    CP_WAIT(2);
    __syncthreads();
#pragma unroll
    for (int i = 0; i < 2; ++i)
#pragma unroll
        for (int j = 0; j < 4; ++j) acc[i][j] = 0.f;

#pragma unroll 8
    for (int d = 0; d < 64; ++d) {
        float4 wv = *(const float4*)&wq[d * 128 + c0];
        float x0 = sx[(r0 + 0) * 64 + d];   // warp-uniform broadcast
        float x1 = sx[(r0 + 1) * 64 + d];
        acc[0][0] += x0 * wv.x; acc[0][1] += x0 * wv.y;
        acc[0][2] += x0 * wv.z; acc[0][3] += x0 * wv.w;
        acc[1][0] += x1 * wv.x; acc[1][1] += x1 * wv.y;
        acc[1][2] += x1 * wv.z; acc[1][3] += x1 * wv.w;
    }
#pragma unroll
    for (int i = 0; i < 2; ++i)
        *(float4*)&sh0[(r0 + i) * 128 + c0] =
            make_float4(acc[i][0], acc[i][1], acc[i][2], acc[i][3]);

    // ---- stage 2: h1 = relu(h0 @ Wl0 + bl0)  (K=128) ----
    CP_WAIT(1);
    __syncthreads();
    {
        float4 bv = __ldg((const float4*)&bl0[c0]);
#pragma unroll
        for (int i = 0; i < 2; ++i) { acc[i][0] = bv.x; acc[i][1] = bv.y; acc[i][2] = bv.z; acc[i][3] = bv.w; }
    }
#pragma unroll 8
    for (int d = 0; d < 128; ++d) {
        float4 wv = *(const float4*)&wl0[d * 128 + c0];
        float x0 = sh0[(r0 + 0) * 128 + d];
        float x1 = sh0[(r0 + 1) * 128 + d];
        acc[0][0] += x0 * wv.x; acc[0][1] += x0 * wv.y;
        acc[0][2] += x0 * wv.z; acc[0][3] += x0 * wv.w;
        acc[1][0] += x1 * wv.x; acc[1][1] += x1 * wv.y;
        acc[1][2] += x1 * wv.z; acc[1][3] += x1 * wv.w;
    }
#pragma unroll
    for (int i = 0; i < 2; ++i)
        *(float4*)&sh1[(r0 + i) * 128 + c0] =
            make_float4(fmaxf(acc[i][0], 0.f), fmaxf(acc[i][1], 0.f),
                        fmaxf(acc[i][2], 0.f), fmaxf(acc[i][3], 0.f));

    // ---- stage 3: h2 = relu(h1 @ Wl1 + bl1); out = h0 + h2 ----
    CP_WAIT(0);
    __syncthreads();
    {
        float4 bv = __ldg((const float4*)&bl1[c0]);
#pragma unroll
        for (int i = 0; i < 2; ++i) { acc[i][0] = bv.x; acc[i][1] = bv.y; acc[i][2] = bv.z; acc[i][3] = bv.w; }
    }
#pragma unroll 8
    for (int d = 0; d < 128; ++d) {
        float4 wv = *(const float4*)&wl1[d * 128 + c0];
        float x0 = sh1[(r0 + 0) * 128 + d];
        float x1 = sh1[(r0 + 1) * 128 + d];
        acc[0][0] += x0 * wv.x; acc[0][1] += x0 * wv.y;
        acc[0][2] += x0 * wv.z; acc[0][3] += x0 * wv.w;
        acc[1][0] += x1 * wv.x; acc[1][1] += x1 * wv.y;
        acc[1][2] += x1 * wv.z; acc[1][3] += x1 * wv.w;
    }
#pragma unroll
    for (int i = 0; i < 2; ++i) {
        const float* h0r = &sh0[(r0 + i) * 128 + c0];
        float4 o = make_float4(h0r[0] + fmaxf(acc[i][0], 0.f),
                               h0r[1] + fmaxf(acc[i][1], 0.f),
                               h0r[2] + fmaxf(acc[i][2], 0.f),
                               h0r[3] + fmaxf(acc[i][3], 0.f));
        *(float4*)&out[(size_t)(row0 + r0 + i) * 128 + c0] = o;
    }
}

// ---------------------------------------------------------------------------
extern "C" void kernel_launch(void* const* d_in, const int* in_sizes, int n_in,
                              void* d_out, int out_size) {
    const float* seqs = (const float*)d_in[0];
    const float* W2   = (const float*)d_in[3];
    const float* p    = (const float*)d_in[6];
    const float* Wq   = (const float*)d_in[7];
    const float* Wl0  = (const float*)d_in[8];
    const float* bl0  = (const float*)d_in[9];
    const float* Wl1  = (const float*)d_in[10];
    const float* bl1  = (const float*)d_in[11];
    float* out = (float*)d_out;

    static bool attr_set = false;
    if (!attr_set) {
        cudaFuncSetAttribute(mlp_kernel,
                             cudaFuncAttributeMaxDynamicSharedMemorySize, 204800);
        attr_set = true;
    }

    attn_kernel<<<NG, 128>>>(seqs, W2, p);
    mlp_kernel<<<NG / 32, 512, 204800>>>(Wq, Wl0, bl0, Wl1, bl1, out);
}

// round 6
// speedup vs baseline: 2.3633x; 1.4397x over previous
#include <cuda_runtime.h>
#include <cuda_bf16.h>
#include <cstdint>

// BS=64, G=64, L=100, D=64. NG=4096 groups.
// softmax shift-invariance: V_last/V_avg/b cancel => attn = softmax_l(seqs[l].(W2@p)).
// lens, W1, W3, b unused.

#define NG   4096
#define L    100
#define D    64

__device__ float g_weighted[NG * D];     // attention-pooled rows

// ---------------------------------------------------------------------------
// helpers
// ---------------------------------------------------------------------------
__device__ __forceinline__ void cp16(unsigned int s_addr, const void* g) {
    asm volatile("cp.async.cg.shared.global [%0], [%1], 16;\n" :: "r"(s_addr), "l"(g));
}
#define CP_COMMIT() asm volatile("cp.async.commit_group;\n" ::: "memory")
#define CP_WAIT(n)  asm volatile("cp.async.wait_group %0;\n" :: "n"(n) : "memory")

__device__ __forceinline__ unsigned long long pk2(float v) {
    unsigned long long r;
    asm("mov.b64 %0, {%1, %1};" : "=l"(r) : "f"(v));
    return r;
}
__device__ __forceinline__ void fma2(unsigned long long& d,
                                     unsigned long long a, unsigned long long b) {
    asm("fma.rn.f32x2 %0, %1, %2, %0;" : "+l"(d) : "l"(a), "l"(b));
}
__device__ __forceinline__ float2 unpk(unsigned long long v) {
    float2 r;
    asm("mov.b64 {%0, %1}, %2;" : "=f"(r.x), "=f"(r.y) : "l"(v));
    return r;
}

// ---------------------------------------------------------------------------
// Kernel 1: attention pooling, 2 groups per block, 256 threads.
// Tile in registers: thread t, chunk k: row=(t>>4)+8k, cols [4*(t&15),+4).
// q = W2@p computed once per block from coalesced-staged W2 in shared.
// ---------------------------------------------------------------------------
__global__ __launch_bounds__(256) void attn_kernel(
    const float* __restrict__ seqs, const float* __restrict__ W2,
    const float* __restrict__ p)
{
    __shared__ float w2s[D * 65];        // stride 65: q-read conflict-free
    __shared__ float ps[D];
    __shared__ float q_s[D];
    __shared__ float attn_sh[2][104];
    __shared__ float red[2][4];
    __shared__ float part4[2][4][16][4];

    const int tid  = threadIdx.x;
    const int half = tid >> 7;
    const int t    = tid & 127;
    const int g    = blockIdx.x * 2 + half;
    const int w    = t >> 5;
    const int lane = t & 31;
    const int c4   = t & 15;
    const int grp  = t >> 4;             // row group 0..7

    // ---- issue tile loads into registers (latency starts now) ----
    const float4* src = (const float4*)(seqs + (size_t)g * (L * D));
    float4 r[13];
#pragma unroll
    for (int k = 0; k < 13; ++k) {
        int idx = t + k * 128;
        if (idx < L * (D / 4)) r[k] = __ldg(src + idx);
        else                   r[k] = make_float4(0.f, 0.f, 0.f, 0.f);
    }

    // ---- coalesced stage of W2 (1024 float4) and p into shared ----
#pragma unroll
    for (int i = 0; i < 4; ++i) {
        int idx = tid + i * 256;          // < 1024
        float4 wv = __ldg((const float4*)W2 + idx);
        int row = idx >> 4, c = idx & 15;
        float* dst = &w2s[row * 65 + c * 4];
        dst[0] = wv.x; dst[1] = wv.y; dst[2] = wv.z; dst[3] = wv.w;
    }
    if (tid >= 64 && tid < 128) ps[tid - 64] = __ldg(p + tid - 64);
    __syncthreads();

    // ---- q[d] = row_d(W2) . p  (conflict-free smem) ----
    if (tid < D) {
        float acc = 0.f;
        const float* row = &w2s[tid * 65];
#pragma unroll 16
        for (int e = 0; e < D; ++e) acc += row[e] * ps[e];
        q_s[tid] = acc;
    }
    __syncthreads();

    // ---- emb: per-thread partial dot + 16-lane segmented shfl reduce ----
    const float4 q4 = *(const float4*)&q_s[c4 * 4];
#pragma unroll
    for (int k = 0; k < 13; ++k) {
        float v = r[k].x * q4.x + r[k].y * q4.y + r[k].z * q4.z + r[k].w * q4.w;
        v += __shfl_xor_sync(0xffffffffu, v, 1);
        v += __shfl_xor_sync(0xffffffffu, v, 2);
        v += __shfl_xor_sync(0xffffffffu, v, 4);
        v += __shfl_xor_sync(0xffffffffu, v, 8);
        int row = grp + 8 * k;
        if (c4 == 0 && row < L) attn_sh[half][row] = v;
    }
    __syncthreads();

    // ---- softmax over L=100 (per half: 4 warps) ----
    float v = (t < L) ? attn_sh[half][t] : -1e30f;
    float m = v;
#pragma unroll
    for (int o = 16; o > 0; o >>= 1) m = fmaxf(m, __shfl_xor_sync(0xffffffffu, m, o));
    if (lane == 0) red[half][w] = m;
    __syncthreads();
    float vmax = fmaxf(fmaxf(red[half][0], red[half][1]),
                       fmaxf(red[half][2], red[half][3]));
    __syncthreads();

    float e = (t < L) ? __expf(v - vmax) : 0.f;
    float sv = e;
#pragma unroll
    for (int o = 16; o > 0; o >>= 1) sv += __shfl_xor_sync(0xffffffffu, sv, o);
    if (lane == 0) red[half][w] = sv;
    __syncthreads();
    float inv = 1.f / (red[half][0] + red[half][1] + red[half][2] + red[half][3]);
    if (t < L) attn_sh[half][t] = e * inv;
    else if (t < 104) attn_sh[half][t] = 0.f;
    __syncthreads();

    // ---- pooling in registers ----
    float4 p4 = make_float4(0.f, 0.f, 0.f, 0.f);
#pragma unroll
    for (int k = 0; k < 13; ++k) {
        float a = attn_sh[half][grp + 8 * k];
        p4.x += a * r[k].x; p4.y += a * r[k].y;
        p4.z += a * r[k].z; p4.w += a * r[k].w;
    }
    p4.x += __shfl_xor_sync(0xffffffffu, p4.x, 16);
    p4.y += __shfl_xor_sync(0xffffffffu, p4.y, 16);
    p4.z += __shfl_xor_sync(0xffffffffu, p4.z, 16);
    p4.w += __shfl_xor_sync(0xffffffffu, p4.w, 16);
    if (lane < 16) *(float4*)&part4[half][w][lane][0] = p4;
    __syncthreads();
    if (t < D) {
        int ci = t >> 2, comp = t & 3;
        float sum = part4[half][0][ci][comp] + part4[half][1][ci][comp]
                  + part4[half][2][ci][comp] + part4[half][3][ci][comp];
        g_weighted[g * D + t] = sum;
    }
}

// ---------------------------------------------------------------------------
// MLP: out = h0 + relu(relu(h0@Wl0+bl0)@Wl1+bl1), h0 = X@Wq.
// grid 128 x 512 threads. 32 rows/block. K split over 2 warp-halves.
// 4 rows x 4 cols per thread; accumulators packed f32x2 (column pairs).
// ---------------------------------------------------------------------------
template<int K, bool RELU, bool BIAS, bool RESID, bool GSTORE>
__device__ __forceinline__ void gemm_stage(
    const float* __restrict__ xb, const float* __restrict__ ws,
    const float* __restrict__ bias, const float* __restrict__ resid,
    float* __restrict__ obuf, float* __restrict__ part,
    int kh, int r0, int c0, int grow0)
{
    unsigned long long acc[4][2];
#pragma unroll
    for (int i = 0; i < 4; ++i) { acc[i][0] = 0ull; acc[i][1] = 0ull; }

    const int dbase = kh * (K / 2);
#pragma unroll 4
    for (int d = 0; d < K / 2; ++d) {
        const int dd = dbase + d;
        const unsigned long long* wp =
            (const unsigned long long*)&ws[dd * 128 + c0];
        unsigned long long b0 = wp[0], b1 = wp[1];   // {wv0,wv1},{wv2,wv3}
#pragma unroll
        for (int i = 0; i < 4; ++i) {
            unsigned long long xd = pk2(xb[(r0 + i) * K + dd]);  // bcast LDS
            fma2(acc[i][0], xd, b0);
            fma2(acc[i][1], xd, b1);
        }
    }

    if (kh) {
#pragma unroll
        for (int i = 0; i < 4; ++i) {
            float2 a = unpk(acc[i][0]), b = unpk(acc[i][1]);
            *(float4*)&part[(r0 + i) * 128 + c0] = make_float4(a.x, a.y, b.x, b.y);
        }
    }
    __syncthreads();
    if (!kh) {
        float4 bv = make_float4(0.f, 0.f, 0.f, 0.f);
        if (BIAS) bv = __ldg((const float4*)&bias[c0]);
#pragma unroll
        for (int i = 0; i < 4; ++i) {
            float4 pv = *(const float4*)&part[(r0 + i) * 128 + c0];
            float2 a = unpk(acc[i][0]), b = unpk(acc[i][1]);
            float4 o = make_float4(a.x + pv.x + bv.x, a.y + pv.y + bv.y,
                                   b.x + pv.z + bv.z, b.y + pv.w + bv.w);
            if (RELU) {
                o.x = fmaxf(o.x, 0.f); o.y = fmaxf(o.y, 0.f);
                o.z = fmaxf(o.z, 0.f); o.w = fmaxf(o.w, 0.f);
            }
            if (RESID) {
                const float* rr = &resid[(r0 + i) * 128 + c0];
                o.x += rr[0]; o.y += rr[1]; o.z += rr[2]; o.w += rr[3];
            }
            if (GSTORE)
                *(float4*)&obuf[(size_t)(grow0 + r0 + i) * 128 + c0] = o;
            else
                *(float4*)&obuf[(r0 + i) * 128 + c0] = o;
        }
    }
}

__global__ __launch_bounds__(512) void mlp_kernel(
    const float* __restrict__ Wq,  const float* __restrict__ Wl0,
    const float* __restrict__ bl0, const float* __restrict__ Wl1,
    const float* __restrict__ bl1, float* __restrict__ out)
{
    extern __shared__ float smem[];
    float* sx   = smem;            // 32x64    =  2048 f
    float* sh0  = smem + 2048;     // 32x128   =  4096 f
    float* sh1  = smem + 6144;     // 32x128   =  4096 f
    float* part = smem + 10240;    // 32x128   =  4096 f
    float* wq   = smem + 14336;    // 64x128   =  8192 f
    float* wl0  = smem + 22528;    // 128x128  = 16384 f
    float* wl1  = smem + 38912;    // 128x128  = 16384 f  (55296 f = 216 KB)

    const int t    = threadIdx.x;
    const int row0 = blockIdx.x * 32;

    const unsigned int sb = (unsigned int)__cvta_generic_to_shared(smem);

    // ---- async staging: G0 = sx + Wq, G1 = Wl0, G2 = Wl1 ----
    {
        const float4* xs = (const float4*)(g_weighted + (size_t)row0 * D);
        cp16(sb + (0 + t * 4) * 4, xs + t);                    // 512 f4
#pragma unroll
        for (int i = 0; i < 4; ++i) {
            int idx = t + i * 512;                             // 2048 f4
            cp16(sb + (14336 + idx * 4) * 4, (const float4*)Wq + idx);
        }
        CP_COMMIT();
#pragma unroll
        for (int i = 0; i < 8; ++i) {
            int idx = t + i * 512;                             // 4096 f4
            cp16(sb + (22528 + idx * 4) * 4, (const float4*)Wl0 + idx);
        }
        CP_COMMIT();
#pragma unroll
        for (int i = 0; i < 8; ++i) {
            int idx = t + i * 512;
            cp16(sb + (38912 + idx * 4) * 4, (const float4*)Wl1 + idx);
        }
        CP_COMMIT();
    }

    const int wr   = t >> 5;          // warp 0..15
    const int kh   = wr >> 3;         // K-half
    const int wh   = wr & 7;          // row-tile within half
    const int r0   = wh * 4;          // rows [r0, r0+4)
    const int c0   = (t & 31) * 4;    // cols [c0, c0+4)

    // ---- stage 1: h0 = X @ Wq  (K=64, no bias/relu) ----
    CP_WAIT(2);
    __syncthreads();
    gemm_stage<64, false, false, false, false>(sx, wq, nullptr, nullptr,
                                               sh0, part, kh, r0, c0, 0);

    // ---- stage 2: h1 = relu(h0 @ Wl0 + bl0) ----
    CP_WAIT(1);
    __syncthreads();
    gemm_stage<128, true, true, false, false>(sh0, wl0, bl0, nullptr,
                                              sh1, part, kh, r0, c0, 0);

    // ---- stage 3: out = h0 + relu(h1 @ Wl1 + bl1) ----
    CP_WAIT(0);
    __syncthreads();
    gemm_stage<128, true, true, true, true>(sh1, wl1, bl1, sh0,
                                            out, part, kh, r0, c0, row0);
}

// ---------------------------------------------------------------------------
extern "C" void kernel_launch(void* const* d_in, const int* in_sizes, int n_in,
                              void* d_out, int out_size) {
    const float* seqs = (const float*)d_in[0];
    const float* W2   = (const float*)d_in[3];
    const float* p    = (const float*)d_in[6];
    const float* Wq   = (const float*)d_in[7];
    const float* Wl0  = (const float*)d_in[8];
    const float* bl0  = (const float*)d_in[9];
    const float* Wl1  = (const float*)d_in[10];
    const float* bl1  = (const float*)d_in[11];
    float* out = (float*)d_out;

    static bool attr_set = false;
    if (!attr_set) {
        cudaFuncSetAttribute(mlp_kernel,
                             cudaFuncAttributeMaxDynamicSharedMemorySize, 221184);
        attr_set = true;
    }

    attn_kernel<<<NG / 2, 256>>>(seqs, W2, p);
    mlp_kernel<<<NG / 32, 512, 221184>>>(Wq, Wl0, bl0, Wl1, bl1, out);
}